// round 1
// baseline (speedup 1.0000x reference)
#include <cuda_runtime.h>

#define B_   32
#define S_   1024
#define ATT_ 512
#define W_   8
#define ROWS_ 8   // s-rows per energy block

// ---------------- scratch (no allocations allowed) ----------------
__device__ float g_qbm[B_ * ATT_];   // dec_h @ Wm^T + bm
__device__ float g_qbc[B_ * ATT_];   // dec_h @ Wc^T + bc
__device__ float g_vnm[ATT_];        // gm * vm / ||vm||
__device__ float g_vnc[ATT_];
__device__ float g_me[B_ * S_];      // monotonic energy
__device__ float g_ce[B_ * S_];      // chunk energy
__device__ float g_beta[B_ * S_];

__device__ __forceinline__ float tanha(float x) {
    float y;
    asm("tanh.approx.f32 %0, %1;" : "=f"(y) : "f"(x));
    return y;
}

// ---------------- K0: weight-normed v -----------------------------
__global__ void k_vnorm(const float* __restrict__ vm, const float* __restrict__ gm,
                        const float* __restrict__ vc, const float* __restrict__ gc) {
    const float* v = blockIdx.x ? vc : vm;
    const float* g = blockIdx.x ? gc : gm;
    float* o       = blockIdx.x ? g_vnc : g_vnm;
    int t = threadIdx.x;          // 512 threads
    float x = v[t];
    float ss = x * x;
    __shared__ float red[16];
    #pragma unroll
    for (int off = 16; off; off >>= 1) ss += __shfl_down_sync(0xffffffffu, ss, off);
    if ((t & 31) == 0) red[t >> 5] = ss;
    __syncthreads();
    __shared__ float s_scale;
    if (t == 0) {
        float a = 0.f;
        #pragma unroll
        for (int i = 0; i < 16; i++) a += red[i];
        s_scale = __ldg(g) / sqrtf(a);
    }
    __syncthreads();
    o[t] = x * s_scale;
}

// ---------------- K1: q = dec_h @ W^T + bias ----------------------
__global__ void k_matvec(const float* __restrict__ dec,
                         const float* __restrict__ Wm, const float* __restrict__ bm,
                         const float* __restrict__ Wc, const float* __restrict__ bc) {
    int b = blockIdx.x;
    const float* W    = blockIdx.y ? Wc : Wm;
    const float* bias = blockIdx.y ? bc : bm;
    float* out        = blockIdx.y ? g_qbc : g_qbm;
    __shared__ float sh[ATT_];
    sh[threadIdx.x] = dec[b * 512 + threadIdx.x];   // 512 threads
    __syncthreads();
    int wid = threadIdx.x >> 5, lane = threadIdx.x & 31;
    for (int a = wid; a < ATT_; a += 16) {
        const float* wr = W + (size_t)a * 512;
        float acc = 0.f;
        #pragma unroll 4
        for (int k = lane; k < 512; k += 32) acc += sh[k] * wr[k];
        #pragma unroll
        for (int off = 16; off; off >>= 1) acc += __shfl_down_sync(0xffffffffu, acc, off);
        if (lane == 0) out[b * ATT_ + a] = acc + bias[a];
    }
}

// ---------------- K2: fused energies over key ---------------------
// grid: (S_/ROWS_, B_), 128 threads. One pass over key computes both energies.
__global__ void k_energy(const float* __restrict__ key,
                         const float* __restrict__ vbm, const float* __restrict__ rm,
                         const float* __restrict__ vbc, const float* __restrict__ rc) {
    int b  = blockIdx.y;
    int sc = blockIdx.x;
    int t  = threadIdx.x;  // 128
    __shared__ float4 sqm[128], sqc[128], svm[128], svc[128];
    sqm[t] = reinterpret_cast<const float4*>(g_qbm + b * ATT_)[t];
    sqc[t] = reinterpret_cast<const float4*>(g_qbc + b * ATT_)[t];
    svm[t] = reinterpret_cast<const float4*>(g_vnm)[t];
    svc[t] = reinterpret_cast<const float4*>(g_vnc)[t];
    __syncthreads();
    float4 qm4 = sqm[t], qc4 = sqc[t], vm4 = svm[t], vc4 = svc[t];
    const float cm = __ldg(vbm) + __ldg(rm);
    const float cc = __ldg(vbc) + __ldg(rc);
    __shared__ float rm_[4], rc_[4];
    int lane = t & 31, wid = t >> 5;

    for (int r = 0; r < ROWS_; r++) {
        int s = sc * ROWS_ + r;
        const float4 k4 = reinterpret_cast<const float4*>(
            key + (((size_t)b * S_ + s) << 9))[t];
        float em = vm4.x * tanha(qm4.x + k4.x) + vm4.y * tanha(qm4.y + k4.y)
                 + vm4.z * tanha(qm4.z + k4.z) + vm4.w * tanha(qm4.w + k4.w);
        float ec = vc4.x * tanha(qc4.x + k4.x) + vc4.y * tanha(qc4.y + k4.y)
                 + vc4.z * tanha(qc4.z + k4.z) + vc4.w * tanha(qc4.w + k4.w);
        #pragma unroll
        for (int off = 16; off; off >>= 1) {
            em += __shfl_down_sync(0xffffffffu, em, off);
            ec += __shfl_down_sync(0xffffffffu, ec, off);
        }
        if (lane == 0) { rm_[wid] = em; rc_[wid] = ec; }
        __syncthreads();
        if (t == 0) {
            g_me[b * S_ + s] = rm_[0] + rm_[1] + rm_[2] + rm_[3] + cm;
            g_ce[b * S_ + s] = rc_[0] + rc_[1] + rc_[2] + rc_[3] + cc;
        }
        __syncthreads();
    }
}

// ---------------- K3: per-batch scans + windows -> beta -----------
__device__ __forceinline__ float blk_scan_sum(float v, int t, float* wa) {
    int lane = t & 31, wid = t >> 5;
    float x = v;
    #pragma unroll
    for (int o = 1; o < 32; o <<= 1) {
        float y = __shfl_up_sync(0xffffffffu, x, o);
        if (lane >= o) x += y;
    }
    if (lane == 31) wa[wid] = x;
    __syncthreads();
    if (wid == 0) {
        float a = wa[lane];
        #pragma unroll
        for (int o = 1; o < 32; o <<= 1) {
            float y = __shfl_up_sync(0xffffffffu, a, o);
            if (lane >= o) a += y;
        }
        wa[lane] = a;
    }
    __syncthreads();
    if (wid > 0) x += wa[wid - 1];
    __syncthreads();
    return x;
}

__device__ __forceinline__ float blk_scan_prod(float v, int t, float* wa) {
    int lane = t & 31, wid = t >> 5;
    float x = v;
    #pragma unroll
    for (int o = 1; o < 32; o <<= 1) {
        float y = __shfl_up_sync(0xffffffffu, x, o);
        if (lane >= o) x *= y;
    }
    if (lane == 31) wa[wid] = x;
    __syncthreads();
    if (wid == 0) {
        float a = wa[lane];
        #pragma unroll
        for (int o = 1; o < 32; o <<= 1) {
            float y = __shfl_up_sync(0xffffffffu, a, o);
            if (lane >= o) a *= y;
        }
        wa[lane] = a;
    }
    __syncthreads();
    if (wid > 0) x *= wa[wid - 1];
    __syncthreads();
    return x;
}

__global__ void k_scan(const float* __restrict__ noise, const float* __restrict__ prev) {
    int b = blockIdx.x, s = threadIdx.x;   // 1024 threads
    const int base = b * S_;
    __shared__ float sm[S_];
    __shared__ float wa[32];

    // p_sel
    float e = g_me[base + s];
    float p = 1.f / (1.f + __expf(-(e + noise[base + s])));
    if (s == S_ - 1) p = 1.f;
    float omp = 1.f - p;

    // exclusive cumprod cp[s] = prod_{i<s}(1-p_i)
    float ip = blk_scan_prod(omp, s, wa);
    sm[s] = ip;
    __syncthreads();
    float cp = (s == 0) ? 1.f : sm[s - 1];
    __syncthreads();

    // normalize prev_att
    float pv = prev[base + s];
    {
        float tsum = pv;
        #pragma unroll
        for (int off = 16; off; off >>= 1) tsum += __shfl_down_sync(0xffffffffu, tsum, off);
        if ((s & 31) == 0) wa[s >> 5] = tsum;
    }
    __syncthreads();
    __shared__ float s_psum;
    if (s == 0) {
        float a = 0.f;
        #pragma unroll
        for (int i = 0; i < 32; i++) a += wa[i];
        s_psum = a;
    }
    __syncthreads();
    float cpc = fminf(fmaxf(cp, 1e-20f), 1.f);
    float y = (pv / s_psum) / cpc;
    float cs = blk_scan_sum(y, s, wa);
    float alpha = p * cp * cs;

    // chunk side
    float c = g_ce[base + s];
    sm[s] = c;
    __syncthreads();
    float mx = c;
    #pragma unroll
    for (int j = 1; j < W_; j++) { int i = s - j; if (i >= 0) mx = fmaxf(mx, sm[i]); }
    float eu = __expf(c - mx);
    __syncthreads();
    sm[s] = eu;
    __syncthreads();
    float den = 0.f;
    #pragma unroll
    for (int j = 0; j < W_; j++) { int i = s - j; if (i >= 0) den += sm[i]; }
    den = fmaxf(den, 1e-10f);
    float g = alpha / den;
    __syncthreads();
    sm[s] = g;
    __syncthreads();
    float acc = 0.f;
    #pragma unroll
    for (int j = 0; j < W_; j++) { int i = s + j; if (i < S_) acc += sm[i]; }
    g_beta[base + s] = eu * acc;
}

// ---------------- K4: context = beta . value ----------------------
__global__ void k_zero(float* __restrict__ out) {
    out[blockIdx.x * 256 + threadIdx.x] = 0.f;
}

#define SCHUNK_ 64
__global__ void k_ctx(const float* __restrict__ value, float* __restrict__ out) {
    int b = blockIdx.y, sc = blockIdx.x;   // 16 chunks of 64
    int d = threadIdx.x;                    // 512
    __shared__ float sb[SCHUNK_];
    if (d < SCHUNK_) sb[d] = g_beta[b * S_ + sc * SCHUNK_ + d];
    __syncthreads();
    const float* vp = value + (((size_t)b * S_ + sc * SCHUNK_) << 9) + d;
    float acc = 0.f;
    #pragma unroll 8
    for (int s = 0; s < SCHUNK_; s++) acc += sb[s] * vp[(size_t)s << 9];
    atomicAdd(&out[b * 512 + d], acc);
}

// ---------------- launch ------------------------------------------
extern "C" void kernel_launch(void* const* d_in, const int* in_sizes, int n_in,
                              void* d_out, int out_size) {
    const float* dec   = (const float*)d_in[0];
    const float* key   = (const float*)d_in[1];
    const float* value = (const float*)d_in[2];
    const float* prev  = (const float*)d_in[3];
    const float* noise = (const float*)d_in[4];
    const float* Wm    = (const float*)d_in[5];
    const float* bm    = (const float*)d_in[6];
    const float* vm    = (const float*)d_in[7];
    const float* gm    = (const float*)d_in[8];
    const float* vbm   = (const float*)d_in[9];
    const float* rm    = (const float*)d_in[10];
    const float* Wc    = (const float*)d_in[11];
    const float* bc    = (const float*)d_in[12];
    const float* vc    = (const float*)d_in[13];
    const float* gc    = (const float*)d_in[14];
    const float* vbc   = (const float*)d_in[15];
    const float* rc    = (const float*)d_in[16];
    float* out = (float*)d_out;

    k_vnorm<<<2, 512>>>(vm, gm, vc, gc);
    k_matvec<<<dim3(B_, 2), 512>>>(dec, Wm, bm, Wc, bc);
    k_energy<<<dim3(S_ / ROWS_, B_), 128>>>(key, vbm, rm, vbc, rc);
    k_scan<<<B_, S_>>>(noise, prev);
    k_zero<<<(B_ * 512) / 256, 256>>>(out);
    k_ctx<<<dim3(S_ / SCHUNK_, B_), 512>>>(value, out);
}

// round 2
// speedup vs baseline: 1.4424x; 1.4424x over previous
#include <cuda_runtime.h>

#define B_   32
#define S_   1024
#define ATT_ 512
#define W_   8

// ---------------- scratch (no allocations allowed) ----------------
__device__ float g_qbm[B_ * ATT_];   // dec_h @ Wm^T + bm
__device__ float g_qbc[B_ * ATT_];   // dec_h @ Wc^T + bc
__device__ float g_vnm[ATT_];        // gm * vm / ||vm||
__device__ float g_vnc[ATT_];
__device__ float g_me[B_ * S_];      // monotonic energy
__device__ float g_ce[B_ * S_];      // chunk energy
__device__ float g_beta[B_ * S_];

__device__ __forceinline__ float tanha(float x) {
    float y;
    asm("tanh.approx.f32 %0, %1;" : "=f"(y) : "f"(x));
    return y;
}

// ---------------- K0: weight-normed v + zero out ------------------
// grid 32 x 512 threads: every block zeros a 512-float slice of out;
// blocks 0/1 additionally compute the weight-normed v vectors.
__global__ void k_vnorm_zero(const float* __restrict__ vm, const float* __restrict__ gm,
                             const float* __restrict__ vc, const float* __restrict__ gc,
                             float* __restrict__ out) {
    int t = threadIdx.x;
    out[blockIdx.x * 512 + t] = 0.f;
    if (blockIdx.x > 1) return;
    const float* v = blockIdx.x ? vc : vm;
    const float* g = blockIdx.x ? gc : gm;
    float* o       = blockIdx.x ? g_vnc : g_vnm;
    float x = v[t];
    float ss = x * x;
    __shared__ float red[16];
    #pragma unroll
    for (int off = 16; off; off >>= 1) ss += __shfl_down_sync(0xffffffffu, ss, off);
    if ((t & 31) == 0) red[t >> 5] = ss;
    __syncthreads();
    __shared__ float s_scale;
    if (t == 0) {
        float a = 0.f;
        #pragma unroll
        for (int i = 0; i < 16; i++) a += red[i];
        s_scale = __ldg(g) / sqrtf(a);
    }
    __syncthreads();
    o[t] = x * s_scale;
}

// ---------------- K1: q = dec_h @ W^T + bias ----------------------
// float4 loads, 4 LDG.128 per row, warp-per-row.
__global__ void __launch_bounds__(512) k_matvec(
        const float* __restrict__ dec,
        const float* __restrict__ Wm, const float* __restrict__ bm,
        const float* __restrict__ Wc, const float* __restrict__ bc) {
    int b = blockIdx.x;
    const float* W    = blockIdx.y ? Wc : Wm;
    const float* bias = blockIdx.y ? bc : bm;
    float* out        = blockIdx.y ? g_qbc : g_qbm;
    __shared__ float4 sh4[128];
    int tid = threadIdx.x;
    if (tid < 128) sh4[tid] = reinterpret_cast<const float4*>(dec + b * 512)[tid];
    __syncthreads();
    int wid = tid >> 5, lane = tid & 31;
    float4 s4[4];
    #pragma unroll
    for (int j = 0; j < 4; j++) s4[j] = sh4[lane + 32 * j];
    for (int a = wid; a < ATT_; a += 16) {
        const float4* wr = reinterpret_cast<const float4*>(W + (size_t)a * 512);
        float acc = 0.f;
        #pragma unroll
        for (int j = 0; j < 4; j++) {
            float4 w4 = wr[lane + 32 * j];
            acc += s4[j].x * w4.x + s4[j].y * w4.y + s4[j].z * w4.z + s4[j].w * w4.w;
        }
        #pragma unroll
        for (int off = 16; off; off >>= 1) acc += __shfl_down_sync(0xffffffffu, acc, off);
        if (lane == 0) out[b * ATT_ + a] = acc + bias[a];
    }
}

// ---------------- K2: fused energies over key ---------------------
// grid (S_/32, B_), 256 threads (8 warps). Warp-per-row, 4 rows/warp,
// NO block barriers. q/v vectors live in registers.
__global__ void __launch_bounds__(256) k_energy(
        const float* __restrict__ key,
        const float* __restrict__ vbm, const float* __restrict__ rm,
        const float* __restrict__ vbc, const float* __restrict__ rc) {
    int b = blockIdx.y, tile = blockIdx.x;
    int w = threadIdx.x >> 5, lane = threadIdx.x & 31;

    const float4* qmp = reinterpret_cast<const float4*>(g_qbm + b * ATT_);
    const float4* qcp = reinterpret_cast<const float4*>(g_qbc + b * ATT_);
    const float4* vmp = reinterpret_cast<const float4*>(g_vnm);
    const float4* vcp = reinterpret_cast<const float4*>(g_vnc);
    float4 qm[4], qc[4], vmr[4], vcr[4];
    #pragma unroll
    for (int j = 0; j < 4; j++) {
        qm[j]  = qmp[lane + 32 * j];
        qc[j]  = qcp[lane + 32 * j];
        vmr[j] = vmp[lane + 32 * j];
        vcr[j] = vcp[lane + 32 * j];
    }
    const float cm = __ldg(vbm) + __ldg(rm);
    const float cc = __ldg(vbc) + __ldg(rc);

    int s0 = tile * 32 + w * 4;
    #pragma unroll
    for (int r = 0; r < 4; r++) {
        int s = s0 + r;
        const float4* kp = reinterpret_cast<const float4*>(key + (((size_t)b * S_ + s) << 9));
        float4 k4[4];
        #pragma unroll
        for (int j = 0; j < 4; j++) k4[j] = kp[lane + 32 * j];
        float em = 0.f, ec = 0.f;
        #pragma unroll
        for (int j = 0; j < 4; j++) {
            em += vmr[j].x * tanha(qm[j].x + k4[j].x) + vmr[j].y * tanha(qm[j].y + k4[j].y)
                + vmr[j].z * tanha(qm[j].z + k4[j].z) + vmr[j].w * tanha(qm[j].w + k4[j].w);
            ec += vcr[j].x * tanha(qc[j].x + k4[j].x) + vcr[j].y * tanha(qc[j].y + k4[j].y)
                + vcr[j].z * tanha(qc[j].z + k4[j].z) + vcr[j].w * tanha(qc[j].w + k4[j].w);
        }
        #pragma unroll
        for (int off = 16; off; off >>= 1) {
            em += __shfl_down_sync(0xffffffffu, em, off);
            ec += __shfl_down_sync(0xffffffffu, ec, off);
        }
        if (lane == 0) {
            g_me[b * S_ + s] = em + cm;
            g_ce[b * S_ + s] = ec + cc;
        }
    }
}

// ---------------- K3: per-batch scans + windows -> beta -----------
__device__ __forceinline__ float blk_scan_sum(float v, int t, float* wa) {
    int lane = t & 31, wid = t >> 5;
    float x = v;
    #pragma unroll
    for (int o = 1; o < 32; o <<= 1) {
        float y = __shfl_up_sync(0xffffffffu, x, o);
        if (lane >= o) x += y;
    }
    if (lane == 31) wa[wid] = x;
    __syncthreads();
    if (wid == 0) {
        float a = wa[lane];
        #pragma unroll
        for (int o = 1; o < 32; o <<= 1) {
            float y = __shfl_up_sync(0xffffffffu, a, o);
            if (lane >= o) a *= 1.f, a += y;   // sum scan
        }
        wa[lane] = a;
    }
    __syncthreads();
    if (wid > 0) x += wa[wid - 1];
    __syncthreads();
    return x;
}

__device__ __forceinline__ float blk_scan_prod(float v, int t, float* wa) {
    int lane = t & 31, wid = t >> 5;
    float x = v;
    #pragma unroll
    for (int o = 1; o < 32; o <<= 1) {
        float y = __shfl_up_sync(0xffffffffu, x, o);
        if (lane >= o) x *= y;
    }
    if (lane == 31) wa[wid] = x;
    __syncthreads();
    if (wid == 0) {
        float a = wa[lane];
        #pragma unroll
        for (int o = 1; o < 32; o <<= 1) {
            float y = __shfl_up_sync(0xffffffffu, a, o);
            if (lane >= o) a *= y;
        }
        wa[lane] = a;
    }
    __syncthreads();
    if (wid > 0) x *= wa[wid - 1];
    __syncthreads();
    return x;
}

__global__ void k_scan(const float* __restrict__ noise, const float* __restrict__ prev) {
    int b = blockIdx.x, s = threadIdx.x;   // 1024 threads
    const int base = b * S_;
    __shared__ float sm[S_];
    __shared__ float wa[32];

    // p_sel
    float e = g_me[base + s];
    float p = 1.f / (1.f + __expf(-(e + noise[base + s])));
    if (s == S_ - 1) p = 1.f;
    float omp = 1.f - p;

    // exclusive cumprod cp[s] = prod_{i<s}(1-p_i)
    float ip = blk_scan_prod(omp, s, wa);
    sm[s] = ip;
    __syncthreads();
    float cp = (s == 0) ? 1.f : sm[s - 1];
    __syncthreads();

    // normalize prev_att
    float pv = prev[base + s];
    {
        float tsum = pv;
        #pragma unroll
        for (int off = 16; off; off >>= 1) tsum += __shfl_down_sync(0xffffffffu, tsum, off);
        if ((s & 31) == 0) wa[s >> 5] = tsum;
    }
    __syncthreads();
    __shared__ float s_psum;
    if (s == 0) {
        float a = 0.f;
        #pragma unroll
        for (int i = 0; i < 32; i++) a += wa[i];
        s_psum = a;
    }
    __syncthreads();
    float cpc = fminf(fmaxf(cp, 1e-20f), 1.f);
    float y = (pv / s_psum) / cpc;
    float cs = blk_scan_sum(y, s, wa);
    float alpha = p * cp * cs;

    // chunk side
    float c = g_ce[base + s];
    sm[s] = c;
    __syncthreads();
    float mx = c;
    #pragma unroll
    for (int j = 1; j < W_; j++) { int i = s - j; if (i >= 0) mx = fmaxf(mx, sm[i]); }
    float eu = __expf(c - mx);
    __syncthreads();
    sm[s] = eu;
    __syncthreads();
    float den = 0.f;
    #pragma unroll
    for (int j = 0; j < W_; j++) { int i = s - j; if (i >= 0) den += sm[i]; }
    den = fmaxf(den, 1e-10f);
    float g = alpha / den;
    __syncthreads();
    sm[s] = g;
    __syncthreads();
    float acc = 0.f;
    #pragma unroll
    for (int j = 0; j < W_; j++) { int i = s + j; if (i < S_) acc += sm[i]; }
    g_beta[base + s] = eu * acc;
}

// ---------------- K4: context = beta . value ----------------------
#define SCHUNK_ 64
__global__ void __launch_bounds__(512) k_ctx(const float* __restrict__ value,
                                             float* __restrict__ out) {
    int b = blockIdx.y, sc = blockIdx.x;   // 16 chunks of 64
    int d = threadIdx.x;                    // 512
    __shared__ float sb[SCHUNK_];
    if (d < SCHUNK_) sb[d] = g_beta[b * S_ + sc * SCHUNK_ + d];
    __syncthreads();
    const float* vp = value + (((size_t)b * S_ + sc * SCHUNK_) << 9) + d;
    float acc = 0.f;
    #pragma unroll 16
    for (int s = 0; s < SCHUNK_; s++) acc += sb[s] * vp[(size_t)s << 9];
    atomicAdd(&out[b * 512 + d], acc);
}

// ---------------- launch ------------------------------------------
extern "C" void kernel_launch(void* const* d_in, const int* in_sizes, int n_in,
                              void* d_out, int out_size) {
    const float* dec   = (const float*)d_in[0];
    const float* key   = (const float*)d_in[1];
    const float* value = (const float*)d_in[2];
    const float* prev  = (const float*)d_in[3];
    const float* noise = (const float*)d_in[4];
    const float* Wm    = (const float*)d_in[5];
    const float* bm    = (const float*)d_in[6];
    const float* vm    = (const float*)d_in[7];
    const float* gm    = (const float*)d_in[8];
    const float* vbm   = (const float*)d_in[9];
    const float* rm    = (const float*)d_in[10];
    const float* Wc    = (const float*)d_in[11];
    const float* bc    = (const float*)d_in[12];
    const float* vc    = (const float*)d_in[13];
    const float* gc    = (const float*)d_in[14];
    const float* vbc   = (const float*)d_in[15];
    const float* rc    = (const float*)d_in[16];
    float* out = (float*)d_out;

    k_vnorm_zero<<<32, 512>>>(vm, gm, vc, gc, out);
    k_matvec<<<dim3(B_, 2), 512>>>(dec, Wm, bm, Wc, bc);
    k_energy<<<dim3(S_ / 32, B_), 256>>>(key, vbm, rm, vbc, rc);
    k_scan<<<B_, S_>>>(noise, prev);
    k_ctx<<<dim3(S_ / SCHUNK_, B_), 512>>>(value, out);
}

// round 3
// speedup vs baseline: 2.4614x; 1.7064x over previous
#include <cuda_runtime.h>

#define B_   32
#define S_   1024
#define ATT_ 512
#define W_   8

// ---------------- scratch (no allocations allowed) ----------------
__device__ float g_qbm[B_ * ATT_];   // dec_h @ Wm^T + bm
__device__ float g_qbc[B_ * ATT_];   // dec_h @ Wc^T + bc
__device__ float g_vnm[ATT_];        // gm * vm / ||vm||
__device__ float g_vnc[ATT_];
__device__ float g_me[B_ * S_];      // monotonic energy
__device__ float g_ce[B_ * S_];      // chunk energy
__device__ float g_beta[B_ * S_];

__device__ __forceinline__ float tanha(float x) {
    float y;
    asm("tanh.approx.f32 %0, %1;" : "=f"(y) : "f"(x));
    return y;
}

// ---------------- K0: matvec + vnorm + zero (fused pre-pass) ------
// grid (32, 3), 256 threads.
//   y=0/1 : q = dec @ W^T + bias for Wm/Wc.  W rows in registers (read once),
//           dec staged through smem in two 32KB halves, warp loops all batches.
//   y=2   : zero d_out; blocks x=0,1 also compute weight-normed v.
__global__ void __launch_bounds__(256) k_pre(
        const float* __restrict__ dec,
        const float* __restrict__ Wm, const float* __restrict__ bm,
        const float* __restrict__ Wc, const float* __restrict__ bc,
        const float* __restrict__ vm, const float* __restrict__ gm,
        const float* __restrict__ vc, const float* __restrict__ gc,
        float* __restrict__ out) {
    int t = threadIdx.x;

    if (blockIdx.y == 2) {
        int x = blockIdx.x;
        out[x * 512 + t] = 0.f;
        out[x * 512 + 256 + t] = 0.f;
        if (x > 1) return;
        const float* v = x ? vc : vm;
        const float* g = x ? gc : gm;
        float* o       = x ? g_vnc : g_vnm;
        float x1 = v[t], x2 = v[t + 256];
        float ss = x1 * x1 + x2 * x2;
        __shared__ float red[8];
        #pragma unroll
        for (int off = 16; off; off >>= 1) ss += __shfl_down_sync(0xffffffffu, ss, off);
        if ((t & 31) == 0) red[t >> 5] = ss;
        __syncthreads();
        __shared__ float s_scale;
        if (t == 0) {
            float a = 0.f;
            #pragma unroll
            for (int i = 0; i < 8; i++) a += red[i];
            s_scale = __ldg(g) / sqrtf(a);
        }
        __syncthreads();
        o[t] = x1 * s_scale;
        o[t + 256] = x2 * s_scale;
        return;
    }

    const float* W    = blockIdx.y ? Wc : Wm;
    const float* bias = blockIdx.y ? bc : bm;
    float* qout       = blockIdx.y ? g_qbc : g_qbm;

    int w = t >> 5, lane = t & 31;
    int row0 = blockIdx.x * 16 + w * 2;          // 2 rows per warp

    // W rows -> registers (coalesced LDG.128, read once per chip)
    const float4* W40 = reinterpret_cast<const float4*>(W + (size_t)row0 * 512);
    const float4* W41 = reinterpret_cast<const float4*>(W + (size_t)(row0 + 1) * 512);
    float4 w0[4], w1[4];
    #pragma unroll
    for (int j = 0; j < 4; j++) { w0[j] = W40[lane + 32 * j]; w1[j] = W41[lane + 32 * j]; }
    float bias0 = bias[row0], bias1 = bias[row0 + 1];

    __shared__ float4 sdec[16 * 128];            // 32 KB: 16 batches
    const float4* dec4 = reinterpret_cast<const float4*>(dec);

    #pragma unroll
    for (int half = 0; half < 2; half++) {
        #pragma unroll
        for (int i = t; i < 2048; i += 256) sdec[i] = dec4[half * 2048 + i];
        __syncthreads();
        #pragma unroll 4
        for (int bb = 0; bb < 16; bb++) {
            int b = half * 16 + bb;
            float a0 = 0.f, a1 = 0.f;
            #pragma unroll
            for (int j = 0; j < 4; j++) {
                float4 dv = sdec[bb * 128 + lane + 32 * j];
                a0 += w0[j].x * dv.x + w0[j].y * dv.y + w0[j].z * dv.z + w0[j].w * dv.w;
                a1 += w1[j].x * dv.x + w1[j].y * dv.y + w1[j].z * dv.z + w1[j].w * dv.w;
            }
            #pragma unroll
            for (int off = 16; off; off >>= 1) {
                a0 += __shfl_down_sync(0xffffffffu, a0, off);
                a1 += __shfl_down_sync(0xffffffffu, a1, off);
            }
            if (lane == 0) {
                qout[b * ATT_ + row0]     = a0 + bias0;
                qout[b * ATT_ + row0 + 1] = a1 + bias1;
            }
        }
        __syncthreads();
    }
}

// ---------------- K1: fused energies over key ---------------------
// grid (S_/32, B_), 256 threads (8 warps). Warp-per-row, 4 rows/warp.
// q/v staged once through smem (8KB L2 per block, not 64KB).
__global__ void __launch_bounds__(256) k_energy(
        const float* __restrict__ key,
        const float* __restrict__ vbm, const float* __restrict__ rm,
        const float* __restrict__ vbc, const float* __restrict__ rc) {
    int b = blockIdx.y, tile = blockIdx.x;
    int t = threadIdx.x, w = t >> 5, lane = t & 31;

    __shared__ float4 sq[512];   // [qm 128 | qc 128 | vm 128 | vc 128]
    if (t < 128) {
        sq[t]       = reinterpret_cast<const float4*>(g_qbm + b * ATT_)[t];
        sq[256 + t] = reinterpret_cast<const float4*>(g_vnm)[t];
    } else {
        int u = t - 128;
        sq[128 + u] = reinterpret_cast<const float4*>(g_qbc + b * ATT_)[u];
        sq[384 + u] = reinterpret_cast<const float4*>(g_vnc)[u];
    }
    __syncthreads();

    float4 qm[4], qc[4], vmr[4], vcr[4];
    #pragma unroll
    for (int j = 0; j < 4; j++) {
        qm[j]  = sq[lane + 32 * j];
        qc[j]  = sq[128 + lane + 32 * j];
        vmr[j] = sq[256 + lane + 32 * j];
        vcr[j] = sq[384 + lane + 32 * j];
    }
    const float cm = __ldg(vbm) + __ldg(rm);
    const float cc = __ldg(vbc) + __ldg(rc);

    int s0 = tile * 32 + w * 4;
    #pragma unroll
    for (int r = 0; r < 4; r++) {
        int s = s0 + r;
        const float4* kp = reinterpret_cast<const float4*>(key + (((size_t)b * S_ + s) << 9));
        float4 k4[4];
        #pragma unroll
        for (int j = 0; j < 4; j++) k4[j] = kp[lane + 32 * j];
        float em = 0.f, ec = 0.f;
        #pragma unroll
        for (int j = 0; j < 4; j++) {
            em += vmr[j].x * tanha(qm[j].x + k4[j].x) + vmr[j].y * tanha(qm[j].y + k4[j].y)
                + vmr[j].z * tanha(qm[j].z + k4[j].z) + vmr[j].w * tanha(qm[j].w + k4[j].w);
            ec += vcr[j].x * tanha(qc[j].x + k4[j].x) + vcr[j].y * tanha(qc[j].y + k4[j].y)
                + vcr[j].z * tanha(qc[j].z + k4[j].z) + vcr[j].w * tanha(qc[j].w + k4[j].w);
        }
        #pragma unroll
        for (int off = 16; off; off >>= 1) {
            em += __shfl_down_sync(0xffffffffu, em, off);
            ec += __shfl_down_sync(0xffffffffu, ec, off);
        }
        if (lane == 0) {
            g_me[b * S_ + s] = em + cm;
            g_ce[b * S_ + s] = ec + cc;
        }
    }
}

// ---------------- K2: per-batch scans + windows -> beta -----------
__device__ __forceinline__ float blk_scan_sum(float v, int t, float* wa) {
    int lane = t & 31, wid = t >> 5;
    float x = v;
    #pragma unroll
    for (int o = 1; o < 32; o <<= 1) {
        float y = __shfl_up_sync(0xffffffffu, x, o);
        if (lane >= o) x += y;
    }
    if (lane == 31) wa[wid] = x;
    __syncthreads();
    if (wid == 0) {
        float a = wa[lane];
        #pragma unroll
        for (int o = 1; o < 32; o <<= 1) {
            float y = __shfl_up_sync(0xffffffffu, a, o);
            if (lane >= o) a += y;
        }
        wa[lane] = a;
    }
    __syncthreads();
    if (wid > 0) x += wa[wid - 1];
    __syncthreads();
    return x;
}

__device__ __forceinline__ float blk_scan_prod(float v, int t, float* wa) {
    int lane = t & 31, wid = t >> 5;
    float x = v;
    #pragma unroll
    for (int o = 1; o < 32; o <<= 1) {
        float y = __shfl_up_sync(0xffffffffu, x, o);
        if (lane >= o) x *= y;
    }
    if (lane == 31) wa[wid] = x;
    __syncthreads();
    if (wid == 0) {
        float a = wa[lane];
        #pragma unroll
        for (int o = 1; o < 32; o <<= 1) {
            float y = __shfl_up_sync(0xffffffffu, a, o);
            if (lane >= o) a *= y;
        }
        wa[lane] = a;
    }
    __syncthreads();
    if (wid > 0) x *= wa[wid - 1];
    __syncthreads();
    return x;
}

__global__ void k_scan(const float* __restrict__ noise, const float* __restrict__ prev) {
    int b = blockIdx.x, s = threadIdx.x;   // 1024 threads
    const int base = b * S_;
    __shared__ float sm[S_];
    __shared__ float wa[32];

    float e = g_me[base + s];
    float p = 1.f / (1.f + __expf(-(e + noise[base + s])));
    if (s == S_ - 1) p = 1.f;
    float omp = 1.f - p;

    float ip = blk_scan_prod(omp, s, wa);
    sm[s] = ip;
    __syncthreads();
    float cp = (s == 0) ? 1.f : sm[s - 1];
    __syncthreads();

    float pv = prev[base + s];
    {
        float tsum = pv;
        #pragma unroll
        for (int off = 16; off; off >>= 1) tsum += __shfl_down_sync(0xffffffffu, tsum, off);
        if ((s & 31) == 0) wa[s >> 5] = tsum;
    }
    __syncthreads();
    __shared__ float s_psum;
    if (s == 0) {
        float a = 0.f;
        #pragma unroll
        for (int i = 0; i < 32; i++) a += wa[i];
        s_psum = a;
    }
    __syncthreads();
    float cpc = fminf(fmaxf(cp, 1e-20f), 1.f);
    float y = (pv / s_psum) / cpc;
    float cs = blk_scan_sum(y, s, wa);
    float alpha = p * cp * cs;

    float c = g_ce[base + s];
    sm[s] = c;
    __syncthreads();
    float mx = c;
    #pragma unroll
    for (int j = 1; j < W_; j++) { int i = s - j; if (i >= 0) mx = fmaxf(mx, sm[i]); }
    float eu = __expf(c - mx);
    __syncthreads();
    sm[s] = eu;
    __syncthreads();
    float den = 0.f;
    #pragma unroll
    for (int j = 0; j < W_; j++) { int i = s - j; if (i >= 0) den += sm[i]; }
    den = fmaxf(den, 1e-10f);
    float g = alpha / den;
    __syncthreads();
    sm[s] = g;
    __syncthreads();
    float acc = 0.f;
    #pragma unroll
    for (int j = 0; j < W_; j++) { int i = s + j; if (i < S_) acc += sm[i]; }
    g_beta[base + s] = eu * acc;
}

// ---------------- K3: context = beta . value ----------------------
#define SCHUNK_ 32
__global__ void __launch_bounds__(512) k_ctx(const float* __restrict__ value,
                                             float* __restrict__ out) {
    int b = blockIdx.y, sc = blockIdx.x;   // 32 chunks of 32
    int d = threadIdx.x;                    // 512
    __shared__ float sb[SCHUNK_];
    if (d < SCHUNK_) sb[d] = g_beta[b * S_ + sc * SCHUNK_ + d];
    __syncthreads();
    const float* vp = value + (((size_t)b * S_ + sc * SCHUNK_) << 9) + d;
    float acc = 0.f;
    #pragma unroll
    for (int s = 0; s < SCHUNK_; s++) acc += sb[s] * vp[(size_t)s << 9];
    atomicAdd(&out[b * 512 + d], acc);
}

// ---------------- launch ------------------------------------------
extern "C" void kernel_launch(void* const* d_in, const int* in_sizes, int n_in,
                              void* d_out, int out_size) {
    const float* dec   = (const float*)d_in[0];
    const float* key   = (const float*)d_in[1];
    const float* value = (const float*)d_in[2];
    const float* prev  = (const float*)d_in[3];
    const float* noise = (const float*)d_in[4];
    const float* Wm    = (const float*)d_in[5];
    const float* bm    = (const float*)d_in[6];
    const float* vm    = (const float*)d_in[7];
    const float* gm    = (const float*)d_in[8];
    const float* vbm   = (const float*)d_in[9];
    const float* rm    = (const float*)d_in[10];
    const float* Wc    = (const float*)d_in[11];
    const float* bc    = (const float*)d_in[12];
    const float* vc    = (const float*)d_in[13];
    const float* gc    = (const float*)d_in[14];
    const float* vbc   = (const float*)d_in[15];
    const float* rc    = (const float*)d_in[16];
    float* out = (float*)d_out;

    k_pre<<<dim3(32, 3), 256>>>(dec, Wm, bm, Wc, bc, vm, gm, vc, gc, out);
    k_energy<<<dim3(S_ / 32, B_), 256>>>(key, vbm, rm, vbc, rc);
    k_scan<<<B_, S_>>>(noise, prev);
    k_ctx<<<dim3(S_ / SCHUNK_, B_), 512>>>(value, out);
}